// round 10
// baseline (speedup 1.0000x reference)
#include <cuda_runtime.h>
#include <math.h>

#define D 32
#define H 128
#define NB 128
#define NSTEPS 8
#define NS 48
#define DTf 0.125f
#define LOG2PI 1.837877066409345483560659472811f

// E[m*H+k] = W2[m,k] * (W1 @ W3)[k,m]   (input-independent)
__device__ float g_E[H * H];
// per-stage activation streams + per-sample partial scalars
__device__ float g_D1[NB * NS * H];
__device__ float g_H2[NB * NS * H];
__device__ float g_S[NB * 2];

static __device__ constexpr float Aa[6][5] = {
    {0.f, 0.f, 0.f, 0.f, 0.f},
    {0.2f, 0.f, 0.f, 0.f, 0.f},
    {3.f/40.f, 9.f/40.f, 0.f, 0.f, 0.f},
    {44.f/45.f, -56.f/15.f, 32.f/9.f, 0.f, 0.f},
    {19372.f/6561.f, -25360.f/2187.f, 64448.f/6561.f, -212.f/729.f, 0.f},
    {9017.f/3168.f, -355.f/33.f, 46732.f/5247.f, 49.f/176.f, -5103.f/18656.f}
};
static __device__ constexpr float Bb[6] = {
    35.f/384.f, 0.f, 500.f/1113.f, 125.f/192.f, -2187.f/6784.f, 11.f/84.f
};
static __device__ constexpr float Cc[6] = {0.f, 0.2f, 0.3f, 0.8f, 8.f/9.f, 1.f};

__global__ void precompute_E_kernel(const float* __restrict__ W1,
                                    const float* __restrict__ W2,
                                    const float* __restrict__ W3) {
    __shared__ float sW1[H * D];
    __shared__ float sw3col[D];
    int m = blockIdx.x;
    int k = threadIdx.x;
    for (int idx = k; idx < H * D; idx += H) sW1[idx] = W1[idx];
    if (k < D) sw3col[k] = W3[k * H + m];
    __syncthreads();
    float acc = 0.f;
#pragma unroll
    for (int j = 0; j < D; j++) acc += sW1[k * D + j] * sw3col[j];
    g_E[m * H + k] = W2[m * H + k] * acc;
}

__device__ __forceinline__ float ftanh(float z) {
    float e = __expf(2.f * z);
    return 1.f - __fdividef(2.f, e + 1.f);
}

// ======================= main ODE kernel (serial chain) =====================
__global__ __launch_bounds__(256, 1)
void ode_kernel(const float* __restrict__ x0,
                const float* __restrict__ W1g,
                const float* __restrict__ u1g,
                const float* __restrict__ b1g,
                const float* __restrict__ W2g,
                const float* __restrict__ b2g,
                const float* __restrict__ W3g,
                const float* __restrict__ b3g,
                const float* __restrict__ precg,
                float* __restrict__ out)
{
    __shared__ __align__(16) float sx[D];
    __shared__ __align__(16) float sh1[H];
    __shared__ __align__(16) float sh2[H];
    __shared__ __align__(16) float skv[6][D];
    __shared__ float sred[12];

    const int tid  = threadIdx.x;
    const int lane = tid & 31;
    const int wid  = tid >> 5;
    const int r2   = tid >> 1;   // hidden row (pair)
    const int half = tid & 1;
    const int r3   = tid >> 3;   // output row (8 threads/row)
    const int sub  = tid & 7;
    const int b    = blockIdx.x;

    // register-resident weights (NO E matrix in this kernel)
    float4 W1h[4], W2h[16], W3c[4];
    {
        const float4* p = (const float4*)(W1g + r2 * D + half * 16);
#pragma unroll
        for (int i = 0; i < 4; i++) W1h[i] = p[i];
        const float4* q = (const float4*)(W2g + r2 * H + half * 64);
#pragma unroll
        for (int i = 0; i < 16; i++) W2h[i] = q[i];
        const float4* w3 = (const float4*)(W3g + r3 * H + sub * 16);
#pragma unroll
        for (int i = 0; i < 4; i++) W3c[i] = w3[i];
    }
    const float u1r = u1g[r2];
    const float b1r = b1g[r2];
    const float b2r = b2g[r2];
    const float b3r = b3g[r3];
    const float prr = precg[r3];

    float* pD1 = g_D1 + b * NS * H + r2;   // writer-side stream pointers
    float* pH2 = g_H2 + b * NS * H + r2;

    float kacc = 0.f;                      // owner-only dkl dot terms
    float xreg = x0[b * D + r3];           // owner (sub==0) stage state
    float yreg = xreg;

    if (tid < D) sx[tid] = x0[b * D + tid];
    __syncthreads();

#pragma unroll 1
    for (int step = 0; step < NSTEPS; step++) {
        const float t0 = (float)step * DTf;
#pragma unroll
        for (int s = 0; s < 6; s++) {
            const float t   = t0 + Cc[s] * DTf;
            const float omt = 1.f - t;
            const float bct = Bb[s];

            // ---- phase A: h1 = tanh(W1 x + t u1 + b1), pair-split ----
            {
                const float4* xv = ((const float4*)sx) + half * 4;
                float a0 = 0.f, a1 = 0.f, a2 = 0.f, a3 = 0.f;
#pragma unroll
                for (int c = 0; c < 4; c++) {
                    float4 w = W1h[c], x4 = xv[c];
                    a0 = fmaf(w.x, x4.x, a0); a1 = fmaf(w.y, x4.y, a1);
                    a2 = fmaf(w.z, x4.z, a2); a3 = fmaf(w.w, x4.w, a3);
                }
                float p = (a0 + a1) + (a2 + a3);
                p += __shfl_xor_sync(0xffffffffu, p, 1);
                float h = ftanh(p + t * u1r + b1r);
                if (!half) {
                    sh1[r2] = h;
                    pD1[0] = fmaf(-h, h, 1.f);   // stream d1 (fire-and-forget)
                }
            }
            __syncthreads();

            // ---- phase B: h2 = tanh(W2 h1 + b2)  (trace work REMOVED) ----
            {
                const float4* hv = ((const float4*)sh1) + half * 16;
                float a0 = 0.f, a1 = 0.f, a2 = 0.f, a3 = 0.f;
#pragma unroll 8
                for (int c = 0; c < 16; c++) {
                    float4 h4 = hv[c], w = W2h[c];
                    a0 = fmaf(w.x, h4.x, a0); a1 = fmaf(w.y, h4.y, a1);
                    a2 = fmaf(w.z, h4.z, a2); a3 = fmaf(w.w, h4.w, a3);
                }
                float pz = (a0 + a1) + (a2 + a3);
                pz += __shfl_xor_sync(0xffffffffu, pz, 1);
                float h2 = ftanh(pz + b2r);
                if (!half) {
                    sh2[r2] = h2;
                    pH2[0] = h2;                 // stream h2
                }
            }
            __syncthreads();
            pD1 += H; pH2 += H;

            // ---- phase C: k = W3 h2 + b3 (8 thr/row) + owner bookkeeping ----
            {
                const float4* hv = ((const float4*)sh2) + sub * 4;
                float a0 = 0.f, a1 = 0.f, a2 = 0.f, a3 = 0.f;
#pragma unroll
                for (int c = 0; c < 4; c++) {
                    float4 w = W3c[c], h4 = hv[c];
                    a0 = fmaf(w.x, h4.x, a0); a1 = fmaf(w.y, h4.y, a1);
                    a2 = fmaf(w.z, h4.z, a2); a3 = fmaf(w.w, h4.w, a3);
                }
                float o = (a0 + a1) + (a2 + a3);
                o += __shfl_xor_sync(0xffffffffu, o, 1);
                o += __shfl_xor_sync(0xffffffffu, o, 2);
                o += __shfl_xor_sync(0xffffffffu, o, 4);
                if (sub == 0) {
                    o += b3r;
                    skv[s][r3] = o;
                    float xs = xreg;
                    float lp = fmaf(-0.5f * xs, xs, -0.5f * LOG2PI);
                    float gl = -prr * xs;
                    float ca = bct * (-0.5f) * omt * omt;
                    float cb = bct * (-0.5f) * omt * (1.f + t);
                    kacc = fmaf(o, fmaf(ca, lp, cb * gl), kacc);
                    float xn;
                    if (s < 5) {
                        float acc = Aa[s + 1][s] * o;
#pragma unroll
                        for (int l = 0; l < s; l++)
                            acc = fmaf(Aa[s + 1][l], skv[l][r3], acc);
                        xn = fmaf(DTf, acc, yreg);
                    } else {
                        float acc = Bb[0] * skv[0][r3] + Bb[2] * skv[2][r3]
                                  + Bb[3] * skv[3][r3] + Bb[4] * skv[4][r3]
                                  + Bb[5] * o;
                        xn = fmaf(DTf, acc, yreg);
                        yreg = xn;
                    }
                    xreg = xn;
                    sx[r3] = xn;
                }
            }
            __syncthreads();
        }
    }

    // ---- z output straight from owner registers ----
    if (sub == 0) out[b * D + r3] = yreg;

    // ---- reduce kacc (owners only; zero elsewhere) + log_px0 ----
#pragma unroll
    for (int o = 16; o; o >>= 1)
        kacc += __shfl_xor_sync(0xffffffffu, kacc, o);
    if (lane == 0) sred[wid] = kacc;
    if (wid == 1) {
        float xv = x0[b * D + lane];
        float lp = fmaf(-0.5f * xv, xv, -0.5f * LOG2PI);
#pragma unroll
        for (int o = 16; o; o >>= 1)
            lp += __shfl_xor_sync(0xffffffffu, lp, o);
        if (lane == 0) sred[8] = lp;
    }
    __syncthreads();
    if (tid == 0) {
        float v3 = sred[0] + sred[1] + sred[2] + sred[3]
                 + sred[4] + sred[5] + sred[6] + sred[7];
        g_S[b * 2 + 0] = sred[8];   // log_px0 sum
        g_S[b * 2 + 1] = v3;        // kacc sum
    }
}

// ============== trace kernel (throughput-parallel, full chip) ===============
__global__ __launch_bounds__(256, 1)
void trace_kernel(float* __restrict__ out)
{
    __shared__ float str[16];
    const int tid  = threadIdx.x;
    const int lane = tid & 31;
    const int wid  = tid >> 5;
    const int r2   = tid >> 1;
    const int half = tid & 1;
    const int b    = blockIdx.x;

    float4 Eh[16];
    {
        const float4* e = (const float4*)(g_E + r2 * H + half * 64);
#pragma unroll
        for (int i = 0; i < 16; i++) Eh[i] = e[i];
    }
    const float* baseD = g_D1 + b * NS * H + half * 64;
    const float* baseH = g_H2 + b * NS * H + r2;

    float accld = 0.f, acckl = 0.f;
#pragma unroll 1
    for (int stp = 0; stp < NSTEPS; stp++) {
        const float t0 = (float)stp * DTf;
#pragma unroll
        for (int s = 0; s < 6; s++) {
            if (s == 1) continue;   // Bb[1] == 0 -> zero contribution
            const int si = stp * 6 + s;
            const float4* dv = (const float4*)(baseD + si * H);
            float g0 = 0.f, g1 = 0.f, g2 = 0.f, g3 = 0.f;
#pragma unroll
            for (int c = 0; c < 16; c++) {
                float4 e = Eh[c], d4 = dv[c];
                g0 = fmaf(e.x, d4.x, g0); g1 = fmaf(e.y, d4.y, g1);
                g2 = fmaf(e.z, d4.z, g2); g3 = fmaf(e.w, d4.w, g3);
            }
            float h2 = baseH[si * H];
            float trp = fmaf(-h2, h2, 1.f) * ((g0 + g1) + (g2 + g3));
            float bct = Bb[s];
            float bco = bct * (1.f - (t0 + Cc[s] * DTf));
            accld = fmaf(bct, trp, accld);
            acckl = fmaf(bco, trp, acckl);
        }
    }

#pragma unroll
    for (int o = 16; o; o >>= 1) {
        accld += __shfl_xor_sync(0xffffffffu, accld, o);
        acckl += __shfl_xor_sync(0xffffffffu, acckl, o);
    }
    if (lane == 0) { str[wid] = accld; str[8 + wid] = acckl; }
    __syncthreads();
    if (tid == 0) {
        float v1 = str[0] + str[1] + str[2] + str[3]
                 + str[4] + str[5] + str[6] + str[7];
        float v2 = str[8] + str[9] + str[10] + str[11]
                 + str[12] + str[13] + str[14] + str[15];
        float lp = g_S[b * 2 + 0];
        float kc = g_S[b * 2 + 1];
        out[NB * D + b]      = lp - DTf * v1;          // log_px0 + log_det
        out[NB * D + NB + b] = DTf * kc - DTf * v2;    // kl
    }
}

extern "C" void kernel_launch(void* const* d_in, const int* in_sizes, int n_in,
                              void* d_out, int out_size) {
    const float* x0   = (const float*)d_in[0];
    const float* W1   = (const float*)d_in[1];
    const float* u1   = (const float*)d_in[2];
    const float* b1   = (const float*)d_in[3];
    const float* W2   = (const float*)d_in[4];
    const float* b2   = (const float*)d_in[5];
    const float* W3   = (const float*)d_in[6];
    const float* b3   = (const float*)d_in[7];
    const float* prec = (const float*)d_in[8];
    float* out = (float*)d_out;

    precompute_E_kernel<<<H, H>>>(W1, W2, W3);
    ode_kernel<<<NB, 256>>>(x0, W1, u1, b1, W2, b2, W3, b3, prec, out);
    trace_kernel<<<NB, 256>>>(out);
}